// round 12
// baseline (speedup 1.0000x reference)
#include <cuda_runtime.h>
#include <cstdint>
#include <cstddef>

#define SEQ   2048
#define BATCH 128
#define HID   256
#define NCTA  128      // 64 clusters * 2 CTAs
#define QSTRIDE 68     // 64 cols + 4 pad floats (bank-shift between quarters)

// ---------------- f32x2 packed helpers (sm_103a) ----------------
__device__ __forceinline__ unsigned long long pk2(float x, float y){
    unsigned long long r; asm("mov.b64 %0, {%1,%2};" : "=l"(r) : "f"(x), "f"(y)); return r;
}
__device__ __forceinline__ void upk2(unsigned long long v, float& x, float& y){
    asm("mov.b64 {%0,%1}, %2;" : "=f"(x), "=f"(y) : "l"(v));
}
__device__ __forceinline__ unsigned long long ffma2(unsigned long long a,
                                                    unsigned long long b,
                                                    unsigned long long c){
    unsigned long long d;
    asm("fma.rn.f32x2 %0, %1, %2, %3;" : "=l"(d) : "l"(a), "l"(b), "l"(c));
    return d;
}

// ---------------- smem / cluster helpers (proven in R5/R8/R9) ----------------
__device__ __forceinline__ unsigned smem_u32(const void* p){
    return (unsigned)__cvta_generic_to_shared(p);
}
__device__ __forceinline__ unsigned mapa_u32(unsigned laddr, unsigned peer){
    unsigned r;
    asm("mapa.shared::cluster.u32 %0, %1, %2;" : "=r"(r) : "r"(laddr), "r"(peer));
    return r;
}
__device__ __forceinline__ void mbar_init(unsigned a, unsigned cnt){
    asm volatile("mbarrier.init.shared.b64 [%0], %1;" :: "r"(a), "r"(cnt) : "memory");
}
__device__ __forceinline__ void mbar_inval(unsigned a){
    asm volatile("mbarrier.inval.shared.b64 [%0];" :: "r"(a) : "memory");
}
__device__ __forceinline__ void st_remote_f(unsigned raddr, float v){
    asm volatile("st.shared::cluster.b32 [%0], %1;" :: "r"(raddr), "f"(v) : "memory");
}
__device__ __forceinline__ void arrive_local(unsigned a){
    asm volatile("mbarrier.arrive.shared.b64 _, [%0];" :: "r"(a) : "memory");
}
__device__ __forceinline__ void arrive_remote(unsigned raddr){
    asm volatile("mbarrier.arrive.release.cluster.shared::cluster.b64 _, [%0];"
                 :: "r"(raddr) : "memory");
}
__device__ __forceinline__ void mbar_wait_acq_cluster(unsigned a, unsigned parity){
    asm volatile(
        "{\n\t.reg .pred P;\n\t"
        "WL_%=:\n\t"
        "mbarrier.try_wait.parity.acquire.cluster.shared::cta.b64 P, [%0], %1, 0x989680;\n\t"
        "@!P bra WL_%=;\n\t"
        "}"
        :: "r"(a), "r"(parity) : "memory");
}
__device__ __forceinline__ void cluster_sync_hw(){
    asm volatile("barrier.cluster.arrive.aligned;" ::: "memory");
    asm volatile("barrier.cluster.wait.aligned;"   ::: "memory");
}
__device__ __forceinline__ unsigned cta_rank(){
    unsigned r; asm("mov.u32 %0, %%cluster_ctarank;" : "=r"(r)); return r;
}
__device__ __forceinline__ float sigmoidf(float x){
    return __fdividef(1.f, 1.f + __expf(-x));
}

// =====================================================================
// Persistent RNN: 64 clusters x 2 CTAs, 2 batches/cluster.
// CTA r owns rows [r*128, r*128+128). Thread = (warp w, lane l):
//   row iloc = w*16 + (l&15); sub-quarter jq = l>>4 covers 128 cols
//   (quarter jq of the local half + quarter jq of the peer half).
// Per step: wait mb_local[cur] -> FFMA local quarter -> wait mb_remote[cur]
//   (hidden: sent one epilogue earlier) -> FFMA peer quarter ->
//   shfl_xor(16) full-row reduce -> finalize (batch jq, row iglob):
//   sigmoid, STG h, STS local a, remote st a, syncwarp, lane0 arrives.
// Zero BAR.SYNC in the steady-state loop.
// =====================================================================
__global__ void __cluster_dims__(2,1,1) __launch_bounds__(256,1)
rnn_kernel(const float* __restrict__ x,      // (SEQ, BATCH)
           const float* __restrict__ h0,     // (BATCH, HID)
           const float* __restrict__ W_ih,   // (HID, 1)
           const float* __restrict__ W_hh,   // (HID, HID)
           const float* __restrict__ W_hhb,  // (HID, HID)
           const float* __restrict__ b_h,    // (HID,)
           const void*  __restrict__ ctxp,   // scalar
           float* __restrict__ outbuf)       // (BATCH, SEQ, HID)
{
    __shared__ __align__(16) float sa[2][2][4 * QSTRIDE];   // [buf][batch][q*68]
    __shared__ float sx[SEQ * 2];
    __shared__ __align__(8) unsigned long long mb[4];       // [buf*2 + kind]

    const int t = (int)threadIdx.x;
    const int w = t >> 5, l = t & 31;
    const unsigned rank = cta_rank();
    const unsigned peer = rank ^ 1u;
    const int cid  = (int)blockIdx.x >> 1;
    const int b0   = cid * 2;
    const int iloc = w * 16 + (l & 15);
    const int iglob = ((int)rank << 7) + iloc;
    const int jq   = l >> 4;
    const int qA   = ((int)rank << 1) + jq;
    const int qB   = ((int)peer << 1) + jq;

    float ctx;
    {
        int   iv = *(const int*)ctxp;
        float fv = *(const float*)ctxp;
        ctx = (iv >= -1000000 && iv <= 1000000) ? (float)iv : fv;
    }

    // ---- weights: row iglob, quarters qA (local) and qB (peer) ----
    unsigned long long wL[32], wP[32];
    {
        const float4* whA = reinterpret_cast<const float4*>(W_hh  + (size_t)iglob * HID + qA * 64);
        const float4* wbA = reinterpret_cast<const float4*>(W_hhb + (size_t)iglob * HID + qA * 64);
        const float4* whB = reinterpret_cast<const float4*>(W_hh  + (size_t)iglob * HID + qB * 64);
        const float4* wbB = reinterpret_cast<const float4*>(W_hhb + (size_t)iglob * HID + qB * 64);
        #pragma unroll
        for (int m = 0; m < 16; ++m){
            float4 a4 = whA[m], c4 = wbA[m];
            wL[2*m]   = pk2(fmaf(ctx, c4.x, a4.x), fmaf(ctx, c4.y, a4.y));
            wL[2*m+1] = pk2(fmaf(ctx, c4.z, a4.z), fmaf(ctx, c4.w, a4.w));
            float4 b4 = whB[m], d4 = wbB[m];
            wP[2*m]   = pk2(fmaf(ctx, d4.x, b4.x), fmaf(ctx, d4.y, b4.y));
            wP[2*m+1] = pk2(fmaf(ctx, d4.z, b4.z), fmaf(ctx, d4.w, b4.w));
        }
    }
    const float win_r = W_ih[iglob];
    const float bh_r  = b_h[iglob];

    for (int idx = t; idx < SEQ * 2; idx += 256){
        sx[idx] = x[(size_t)(idx >> 1) * BATCH + b0 + (idx & 1)];
    }
    {
        int j = t, q = j >> 6, off = j & 63;
        sa[0][0][q * QSTRIDE + off] = fmaf(2.f, h0[(size_t)b0 * HID + j], -1.f);
        sa[0][1][q * QSTRIDE + off] = fmaf(2.f, h0[(size_t)(b0 + 1) * HID + j], -1.f);
    }
    const unsigned mb_l = smem_u32(&mb[0]);
    if (t == 0){
        #pragma unroll
        for (int s = 0; s < 4; ++s) mbar_init(mb_l + s*8, 8);
    }
    __syncthreads();
    cluster_sync_hw();

    const unsigned sa_u32 = smem_u32(&sa[0][0][0]);
    const unsigned sa_r   = mapa_u32(sa_u32, peer);
    const unsigned mb_r   = mapa_u32(mb_l, peer);

    if (l == 0){                       // prime buffer 0 (data synced above)
        arrive_local(mb_l + 0u);       // mb[0]: buf0 local
        arrive_remote(mb_r + 8u);      // peer mb[1]: buf0 remote
    }

    float* outp = outbuf + (size_t)(b0 + jq) * SEQ * HID + iglob;
    const unsigned aoff = (unsigned)((jq * 4 + (iglob >> 6)) * QSTRIDE + (iglob & 63)) * 4u;
    const unsigned abuf = (unsigned)(2 * 4 * QSTRIDE) * 4u;   // bytes per buffer

    int ph_l[2] = {0, 0}, ph_r[2] = {0, 0};
    int cur = 0;

    for (int step = 0; step < SEQ; ++step){
        const int nxt = cur ^ 1;

        mbar_wait_acq_cluster(mb_l + (unsigned)(cur*2)*8u, (unsigned)ph_l[cur]);
        ph_l[cur] ^= 1;

        unsigned long long acc00 = 0ull, acc01 = 0ull, acc10 = 0ull, acc11 = 0ull;
        {
            const ulonglong2* a0p = reinterpret_cast<const ulonglong2*>(&sa[cur][0][qA * QSTRIDE]);
            const ulonglong2* a1p = reinterpret_cast<const ulonglong2*>(&sa[cur][1][qA * QSTRIDE]);
            #pragma unroll
            for (int m = 0; m < 16; ++m){
                ulonglong2 A0 = a0p[m];
                ulonglong2 A1 = a1p[m];
                acc00 = ffma2(wL[2*m],   A0.x, acc00);
                acc01 = ffma2(wL[2*m+1], A0.y, acc01);
                acc10 = ffma2(wL[2*m],   A1.x, acc10);
                acc11 = ffma2(wL[2*m+1], A1.y, acc11);
            }
        }

        mbar_wait_acq_cluster(mb_l + (unsigned)(cur*2 + 1)*8u, (unsigned)ph_r[cur]);
        ph_r[cur] ^= 1;

        {
            const ulonglong2* a0p = reinterpret_cast<const ulonglong2*>(&sa[cur][0][qB * QSTRIDE]);
            const ulonglong2* a1p = reinterpret_cast<const ulonglong2*>(&sa[cur][1][qB * QSTRIDE]);
            #pragma unroll
            for (int m = 0; m < 16; ++m){
                ulonglong2 A0 = a0p[m];
                ulonglong2 A1 = a1p[m];
                acc00 = ffma2(wP[2*m],   A0.x, acc00);
                acc01 = ffma2(wP[2*m+1], A0.y, acc01);
                acc10 = ffma2(wP[2*m],   A1.x, acc10);
                acc11 = ffma2(wP[2*m+1], A1.y, acc11);
            }
        }

        float s0a, s0b, s0c, s0d, s1a, s1b, s1c, s1d;
        upk2(acc00, s0a, s0b); upk2(acc01, s0c, s0d);
        upk2(acc10, s1a, s1b); upk2(acc11, s1c, s1d);
        float p0 = (s0a + s0b) + (s0c + s0d);
        float p1 = (s1a + s1b) + (s1c + s1d);
        float q0 = __shfl_xor_sync(0xFFFFFFFFu, p0, 16);
        float q1 = __shfl_xor_sync(0xFFFFFFFFu, p1, 16);
        float mysum = jq ? (p1 + q1) : (p0 + q0);

        float pre = mysum + fmaf(sx[2*step + jq], win_r, bh_r);
        float hv  = sigmoidf(pre);
        outp[(size_t)step * HID] = hv;
        float av = fmaf(2.f, hv, -1.f);
        const unsigned dst = (unsigned)nxt * abuf + aoff;
        *reinterpret_cast<float*>(reinterpret_cast<char*>(&sa[0][0][0]) + dst) = av;
        st_remote_f(sa_r + dst, av);
        __syncwarp();
        if (l == 0){
            arrive_local(mb_l + (unsigned)(nxt*2)*8u);
            arrive_remote(mb_r + (unsigned)(nxt*2 + 1)*8u);
        }

        cur = nxt;
    }

    cluster_sync_hw();
    if (t == 0){
        #pragma unroll
        for (int s = 0; s < 4; ++s) mbar_inval(mb_l + s*8);
    }
}

// =====================================================================
// y[b,t] = out[b,t,:] . W[0,:] + b[0]   (one warp per (b,t) row)
// =====================================================================
__global__ void __launch_bounds__(256)
y_kernel(const float* __restrict__ outbuf,
         const float* __restrict__ W,
         const float* __restrict__ bb,
         float* __restrict__ y)
{
    int row  = (int)blockIdx.x * 8 + ((int)threadIdx.x >> 5);
    int lane = (int)threadIdx.x & 31;
    const float4* p  = reinterpret_cast<const float4*>(outbuf + (size_t)row * HID);
    const float4* wp = reinterpret_cast<const float4*>(W);
    float4 a = p[lane*2],  b4 = p[lane*2 + 1];
    float4 u = wp[lane*2], v  = wp[lane*2 + 1];
    float s = a.x*u.x + a.y*u.y + a.z*u.z + a.w*u.w
            + b4.x*v.x + b4.y*v.y + b4.z*v.z + b4.w*v.w;
    #pragma unroll
    for (int off = 16; off; off >>= 1) s += __shfl_xor_sync(0xFFFFFFFFu, s, off);
    if (lane == 0) y[row] = s + bb[0];
}

extern "C" void kernel_launch(void* const* d_in, const int* in_sizes, int n_in,
                              void* d_out, int out_size)
{
    const float* x     = (const float*)d_in[0];
    const float* h0    = (const float*)d_in[1];
    const float* W_ih  = (const float*)d_in[2];
    const float* W_hh  = (const float*)d_in[3];
    const float* W_hhb = (const float*)d_in[4];
    const float* b_h   = (const float*)d_in[5];
    const float* W     = (const float*)d_in[6];
    const float* b     = (const float*)d_in[7];
    const void*  ctx   = d_in[8];

    float* y      = (float*)d_out;
    float* outbuf = y + (size_t)BATCH * SEQ;

    rnn_kernel<<<NCTA, 256>>>(x, h0, W_ih, W_hh, W_hhb, b_h, ctx, outbuf);
    y_kernel<<<(BATCH * SEQ) / 8, 256>>>(outbuf, W, b, y);
}